// round 16
// baseline (speedup 1.0000x reference)
#include <cuda_runtime.h>
#include <cstring>

#define NLAYERS 200
#define KSIZE   7
#define L_IN    1388
#define FC_IN   188
#define FC_OUT  91
#define WPC     7          // 7 rows per CTA, one CTA per SM (147 CTAs for 1024 rows)
#define NT      (32 * WPC)
#define STG_N   1408       // per-warp float stage (2*32*22)

// Conv weights+bias packed per layer as 4 float4:
//   [ (w0,w0,w1,w1), (w2,w2,w3,w3), (w4,w4,w5,w5), (w6,w6,b,b) ]
// -> 4x LDC.128 per layer instead of 8x LDC.64 (LDC floor = 8 cyc each).
__constant__ float4 cwb[NLAYERS * 4];

// Packed dual-fp32 FMA (Blackwell f32x2).
static __device__ __forceinline__ float2 ffma2(float2 a, float2 b, float2 c) {
    unsigned long long ua, ub, uc, ud;
    memcpy(&ua, &a, 8); memcpy(&ub, &b, 8); memcpy(&uc, &c, 8);
    asm("fma.rn.f32x2 %0, %1, %2, %3;" : "=l"(ud) : "l"(ua), "l"(ub), "l"(uc));
    float2 d; memcpy(&d, &ud, 8);
    return d;
}

// Far-pair layout: lane l owns packed positions g = l*C + c, c<C, where
// P[g] = (h[g], h[g+D]) and 32*C == D. Conv taps are ALL pair-aligned:
// P'[g] = sum_k w[k]*P[g+k]. Halo = next lane's first 6 pairs via rotated
// SHFL; lane 31 (seam) takes lane0's .y (the wrong .x only feeds y-half
// tail garbage, which stays right of the shrinking valid length).
template<int C>
static __device__ __forceinline__ void phase(float2* p, int layer0, int nl,
                                             int lane)
{
    static_assert(C >= 6, "seam halo spans one lane only");
    float4 wb0 = cwb[layer0 * 4 + 0];
    float4 wb1 = cwb[layer0 * 4 + 1];
    float4 wb2 = cwb[layer0 * 4 + 2];
    float4 wb3 = cwb[layer0 * 4 + 3];

    #pragma unroll 1
    for (int i = 0; i < nl; i++) {
        const int L = layer0 + i;
        const float2 w0 = make_float2(wb0.x, wb0.y);
        const float2 w1 = make_float2(wb0.z, wb0.w);
        const float2 w2 = make_float2(wb1.x, wb1.y);
        const float2 w3 = make_float2(wb1.z, wb1.w);
        const float2 w4 = make_float2(wb2.x, wb2.y);
        const float2 w5 = make_float2(wb2.z, wb2.w);
        const float2 w6 = make_float2(wb3.x, wb3.y);
        const float2 b  = make_float2(wb3.z, wb3.w);

        const int Lp = (L + 1 < NLAYERS) ? L + 1 : L;   // prefetch next layer
        wb0 = cwb[Lp * 4 + 0];
        wb1 = cwb[Lp * 4 + 1];
        wb2 = cwb[Lp * 4 + 2];
        wb3 = cwb[Lp * 4 + 3];

        float2 rot[6];
        #pragma unroll
        for (int m = 0; m < 6; m++) {
            float rx = __shfl_sync(0xffffffffu, p[m].x, lane + 1); // 31 wraps to 0
            float ry = __shfl_sync(0xffffffffu, p[m].y, lane + 1);
            rot[m] = make_float2((lane == 31) ? ry : rx, ry);
        }

        const bool relu = (L != NLAYERS - 1);
        #pragma unroll
        for (int j = 0; j < C; j++) {
            float2 acc = b;
            acc = ffma2(w0, p[j], acc);
            acc = ffma2(w1, (j + 1 < C) ? p[j + 1] : rot[j + 1 - C], acc);
            acc = ffma2(w2, (j + 2 < C) ? p[j + 2] : rot[j + 2 - C], acc);
            acc = ffma2(w3, (j + 3 < C) ? p[j + 3] : rot[j + 3 - C], acc);
            acc = ffma2(w4, (j + 4 < C) ? p[j + 4] : rot[j + 4 - C], acc);
            acc = ffma2(w5, (j + 5 < C) ? p[j + 5] : rot[j + 5 - C], acc);
            acc = ffma2(w6, (j + 6 < C) ? p[j + 6] : rot[j + 6 - C], acc);
            if (relu) { acc.x = fmaxf(acc.x, 0.0f); acc.y = fmaxf(acc.y, 0.0f); }
            p[j] = acc;   // ascending in-place: p[j] only read by outputs <= j
        }
    }
}

// Re-split from (DO=32*CO, CO) to (DN=32*CN, CN) through the per-warp stage.
// VF = valid element count at the fold layer.
template<int CO, int CN, int VF>
static __device__ __forceinline__ void fold(float2* p, float* stg, int lane)
{
    const int DO = 32 * CO, DN = 32 * CN;
    __syncwarp();
    #pragma unroll
    for (int c = 0; c < CO; c++) {
        int g = lane * CO + c;
        stg[g] = p[c].x;                       // x half: h[0..DO)
        if (DO + g < VF) stg[DO + g] = p[c].y; // y half: h[DO..VF)
    }
    for (int j = VF + lane; j < 2 * DN; j += 32) stg[j] = 0.0f;
    __syncwarp();
    #pragma unroll
    for (int c = 0; c < CN; c++) {
        int g = lane * CN + c;
        p[c] = make_float2(stg[g], stg[g + DN]);
    }
    __syncwarp();
}

__global__ __launch_bounds__(NT, 1)
void conv200_kernel(const float* __restrict__ x,
                    const float* __restrict__ fc_w,
                    const float* __restrict__ fc_b,
                    float* __restrict__ out,
                    int nrows)
{
    __shared__ __align__(16) float stg_all[WPC][STG_N];   // 38.5 KB per-warp stages

    const int t    = threadIdx.x;
    const int wid  = t >> 5;
    const int lane = t & 31;

    const int row = blockIdx.x * WPC + wid;   // one warp = one row
    if (row >= nrows) return;
    const float* xr = x + (size_t)row * L_IN;
    float* stg = stg_all[wid];

    // ---- initial far-pair pack: D=704, C=22 (single pass, big stage) ----
    for (int j = lane; j < STG_N; j += 32)
        stg[j] = (j < L_IN) ? __ldg(&xr[j]) : 0.0f;
    __syncwarp();
    float2 p[22];
    #pragma unroll
    for (int c = 0; c < 22; c++) {
        int g = lane * 22 + c;
        p[c] = make_float2(stg[g], stg[704 + g]);
    }

    // ---- 200 layers: fold at every integer C (width tracks V = 1388-6i) ----
    phase<22>(p,   0,  8, lane); fold<22, 21, 1340>(p, stg, lane);
    phase<21>(p,   8, 10, lane); fold<21, 20, 1280>(p, stg, lane);
    phase<20>(p,  18, 11, lane); fold<20, 19, 1214>(p, stg, lane);
    phase<19>(p,  29, 11, lane); fold<19, 18, 1148>(p, stg, lane);
    phase<18>(p,  40, 10, lane); fold<18, 17, 1088>(p, stg, lane);
    phase<17>(p,  50, 11, lane); fold<17, 16, 1022>(p, stg, lane);
    phase<16>(p,  61, 11, lane); fold<16, 15,  956>(p, stg, lane);
    phase<15>(p,  72, 10, lane); fold<15, 14,  896>(p, stg, lane);
    phase<14>(p,  82, 11, lane); fold<14, 13,  830>(p, stg, lane);
    phase<13>(p,  93, 11, lane); fold<13, 12,  764>(p, stg, lane);
    phase<12>(p, 104, 10, lane); fold<12, 11,  704>(p, stg, lane);
    phase<11>(p, 114, 11, lane); fold<11, 10,  638>(p, stg, lane);
    phase<10>(p, 125, 11, lane); fold<10,  9,  572>(p, stg, lane);
    phase< 9>(p, 136, 10, lane); fold< 9,  8,  512>(p, stg, lane);
    phase< 8>(p, 146, 11, lane); fold< 8,  7,  446>(p, stg, lane);
    phase< 7>(p, 157, 11, lane); fold< 7,  6,  380>(p, stg, lane);
    phase< 6>(p, 168, 32, lane);                       // D=192, final V=188

    // ---- gather final 188 elements (all in x half) ----
    __syncwarp();
    #pragma unroll
    for (int c = 0; c < 6; c++) stg[lane * 6 + c] = p[c].x;   // fills [0,192)
    __syncwarp();

    // ---- FC 188->91 + sigmoid: lane handles outputs {lane, lane+32, lane+64} ----
    {
        const float2* hv2 = reinterpret_cast<const float2*>(stg);
        const float2* fw2 = reinterpret_cast<const float2*>(fc_w);
        float2 acc[3];
        #pragma unroll
        for (int u = 0; u < 3; u++) acc[u] = make_float2(0.0f, 0.0f);
        int o0 = lane, o1 = lane + 32, o2 = lane + 64;
        int c2 = (o2 < FC_OUT) ? o2 : (FC_OUT - 1);
        const float2* r0w = fw2 + (size_t)o0 * (FC_IN / 2);
        const float2* r1w = fw2 + (size_t)o1 * (FC_IN / 2);
        const float2* r2w = fw2 + (size_t)c2 * (FC_IN / 2);
        #pragma unroll 2
        for (int j = 0; j < FC_IN / 2; j++) {
            float2 hv = hv2[j];
            acc[0] = ffma2(__ldg(&r0w[j]), hv, acc[0]);
            acc[1] = ffma2(__ldg(&r1w[j]), hv, acc[1]);
            acc[2] = ffma2(__ldg(&r2w[j]), hv, acc[2]);
        }
        float* orow = out + (size_t)row * FC_OUT;
        float s0 = acc[0].x + acc[0].y + __ldg(&fc_b[o0]);
        float s1 = acc[1].x + acc[1].y + __ldg(&fc_b[o1]);
        orow[o0] = 1.0f / (1.0f + __expf(-s0));
        orow[o1] = 1.0f / (1.0f + __expf(-s1));
        if (o2 < FC_OUT) {
            float s2 = acc[2].x + acc[2].y + __ldg(&fc_b[o2]);
            orow[o2] = 1.0f / (1.0f + __expf(-s2));
        }
    }
}

extern "C" void kernel_launch(void* const* d_in, const int* in_sizes, int n_in,
                              void* d_out, int out_size)
{
    const float* x      = (const float*)d_in[0];   // [1024, 1388]
    const float* conv_w = (const float*)d_in[1];   // [200, 7]
    const float* conv_b = (const float*)d_in[2];   // [200]
    const float* fc_w   = (const float*)d_in[3];   // [91, 188]
    const float* fc_b   = (const float*)d_in[4];   // [91]
    float* out          = (float*)d_out;           // [1024, 91]

    // Pack per-layer (w,w) pairs + (b,b) into cwb[L] = 4 float4 (64B/layer)
    // with pitched D2D copies (graph-capturable memcpy nodes; no allocs).
    char* wp = nullptr;
    cudaGetSymbolAddress((void**)&wp, cwb);
    for (int k = 0; k < KSIZE; k++) {
        // weight k of each layer -> byte offset L*64 + k*8 (+0 and +4)
        cudaMemcpy2DAsync(wp + k * 8,     64, conv_w + k, 28, 4, NLAYERS,
                          cudaMemcpyDeviceToDevice);
        cudaMemcpy2DAsync(wp + k * 8 + 4, 64, conv_w + k, 28, 4, NLAYERS,
                          cudaMemcpyDeviceToDevice);
    }
    // bias -> byte offset L*64 + 56 (+0 and +4)
    cudaMemcpy2DAsync(wp + 56, 64, conv_b, 4, 4, NLAYERS,
                      cudaMemcpyDeviceToDevice);
    cudaMemcpy2DAsync(wp + 60, 64, conv_b, 4, 4, NLAYERS,
                      cudaMemcpyDeviceToDevice);

    const int B = in_sizes[0] / L_IN;              // 1024 rows
    const int grid = (B + WPC - 1) / WPC;          // 147 CTAs (~one per SM)
    conv200_kernel<<<grid, NT>>>(x, fc_w, fc_b, out, B);
}

// round 17
// speedup vs baseline: 1.1616x; 1.1616x over previous
#include <cuda_runtime.h>
#include <cstring>

#define NLAYERS 200
#define KSIZE   7
#define L_IN    1388
#define FC_IN   188
#define FC_OUT  91
#define WPC     7          // warps per CTA; grid=148 (>=148: I$ issue-throttle off)
#define GRID    148
#define NT      (32 * WPC)
#define STG_N   1408       // per-warp float stage (2*32*22)

// Conv weights/biases pre-packed as (w,w)/(b,b) in constant memory.
__constant__ float2 cws[NLAYERS * KSIZE];
__constant__ float2 cbs[NLAYERS];

// Packed dual-fp32 FMA (Blackwell f32x2).
static __device__ __forceinline__ float2 ffma2(float2 a, float2 b, float2 c) {
    unsigned long long ua, ub, uc, ud;
    memcpy(&ua, &a, 8); memcpy(&ub, &b, 8); memcpy(&uc, &c, 8);
    asm("fma.rn.f32x2 %0, %1, %2, %3;" : "=l"(ud) : "l"(ua), "l"(ub), "l"(uc));
    float2 d; memcpy(&d, &ud, 8);
    return d;
}

// Far-pair layout: lane l owns packed positions g = l*C + c, c<C, where
// P[g] = (h[g], h[g+D]) and 32*C == D. Conv taps are ALL pair-aligned:
// P'[g] = sum_k w[k]*P[g+k]. Halo = next lane's first 6 pairs via rotated
// SHFL; lane 31 (seam) takes lane0's .y (the wrong .x only feeds y-half
// tail garbage, which stays right of the shrinking valid length).
template<int C>
static __device__ __forceinline__ void phase(float2* p, int layer0, int nl,
                                             int lane)
{
    static_assert(C >= 6, "seam halo spans one lane only");
    float2 wb[KSIZE + 1];
    #pragma unroll
    for (int k = 0; k < KSIZE; k++) wb[k] = cws[layer0 * KSIZE + k];
    wb[KSIZE] = cbs[layer0];

    #pragma unroll 1
    for (int i = 0; i < nl; i++) {
        const int L = layer0 + i;
        float2 w[KSIZE];
        #pragma unroll
        for (int k = 0; k < KSIZE; k++) w[k] = wb[k];
        const float2 b = wb[KSIZE];

        const int Lp = (L + 1 < NLAYERS) ? L + 1 : L;   // prefetch next layer
        #pragma unroll
        for (int k = 0; k < KSIZE; k++) wb[k] = cws[Lp * KSIZE + k];
        wb[KSIZE] = cbs[Lp];

        float2 rot[6];
        #pragma unroll
        for (int m = 0; m < 6; m++) {
            float rx = __shfl_sync(0xffffffffu, p[m].x, lane + 1); // 31 wraps to 0
            float ry = __shfl_sync(0xffffffffu, p[m].y, lane + 1);
            rot[m] = make_float2((lane == 31) ? ry : rx, ry);
        }

        const bool relu = (L != NLAYERS - 1);
        #pragma unroll
        for (int j = 0; j < C; j++) {
            float2 acc = b;
            acc = ffma2(w[0], p[j], acc);
            #pragma unroll
            for (int k = 1; k < KSIZE; k++) {
                float2 v = (j + k < C) ? p[j + k] : rot[j + k - C];
                acc = ffma2(w[k], v, acc);
            }
            if (relu) { acc.x = fmaxf(acc.x, 0.0f); acc.y = fmaxf(acc.y, 0.0f); }
            p[j] = acc;   // ascending in-place: p[j] only read by outputs <= j
        }
    }
}

// Re-split from (DO=32*CO, CO) to (DN=32*CN, CN) through the per-warp stage.
// VF = valid element count at the fold layer.
template<int CO, int CN, int VF>
static __device__ __forceinline__ void fold(float2* p, float* stg, int lane)
{
    const int DO = 32 * CO, DN = 32 * CN;
    __syncwarp();
    #pragma unroll
    for (int c = 0; c < CO; c++) {
        int g = lane * CO + c;
        stg[g] = p[c].x;                       // x half: h[0..DO)
        if (DO + g < VF) stg[DO + g] = p[c].y; // y half: h[DO..VF)
    }
    for (int j = VF + lane; j < 2 * DN; j += 32) stg[j] = 0.0f;
    __syncwarp();
    #pragma unroll
    for (int c = 0; c < CN; c++) {
        int g = lane * CN + c;
        p[c] = make_float2(stg[g], stg[g + DN]);
    }
    __syncwarp();
}

__global__ __launch_bounds__(NT, 1)
void conv200_kernel(const float* __restrict__ x,
                    const float* __restrict__ fc_w,
                    const float* __restrict__ fc_b,
                    float* __restrict__ out,
                    int nrows)
{
    __shared__ __align__(16) float stg_all[WPC][STG_N];   // 38.5 KB per-warp stages

    const int t    = threadIdx.x;
    const int wid  = t >> 5;
    const int lane = t & 31;

    // row remap: every SM gets one CTA; warp w of CTA b handles row w*GRID+b.
    const int row = wid * GRID + blockIdx.x;
    if (row >= nrows) return;     // whole-warp exit; no block barriers below
    const float* xr = x + (size_t)row * L_IN;
    float* stg = stg_all[wid];

    // ---- initial far-pair pack: D=704, C=22 (single pass, big stage) ----
    for (int j = lane; j < STG_N; j += 32)
        stg[j] = (j < L_IN) ? __ldg(&xr[j]) : 0.0f;
    __syncwarp();
    float2 p[22];
    #pragma unroll
    for (int c = 0; c < 22; c++) {
        int g = lane * 22 + c;
        p[c] = make_float2(stg[g], stg[704 + g]);
    }

    // ---- 200 layers: fold at every integer C (width tracks V = 1388-6i) ----
    phase<22>(p,   0,  8, lane); fold<22, 21, 1340>(p, stg, lane);
    phase<21>(p,   8, 10, lane); fold<21, 20, 1280>(p, stg, lane);
    phase<20>(p,  18, 11, lane); fold<20, 19, 1214>(p, stg, lane);
    phase<19>(p,  29, 11, lane); fold<19, 18, 1148>(p, stg, lane);
    phase<18>(p,  40, 10, lane); fold<18, 17, 1088>(p, stg, lane);
    phase<17>(p,  50, 11, lane); fold<17, 16, 1022>(p, stg, lane);
    phase<16>(p,  61, 11, lane); fold<16, 15,  956>(p, stg, lane);
    phase<15>(p,  72, 10, lane); fold<15, 14,  896>(p, stg, lane);
    phase<14>(p,  82, 11, lane); fold<14, 13,  830>(p, stg, lane);
    phase<13>(p,  93, 11, lane); fold<13, 12,  764>(p, stg, lane);
    phase<12>(p, 104, 10, lane); fold<12, 11,  704>(p, stg, lane);
    phase<11>(p, 114, 11, lane); fold<11, 10,  638>(p, stg, lane);
    phase<10>(p, 125, 11, lane); fold<10,  9,  572>(p, stg, lane);
    phase< 9>(p, 136, 10, lane); fold< 9,  8,  512>(p, stg, lane);
    phase< 8>(p, 146, 11, lane); fold< 8,  7,  446>(p, stg, lane);
    phase< 7>(p, 157, 11, lane); fold< 7,  6,  380>(p, stg, lane);
    phase< 6>(p, 168, 32, lane);                       // D=192, final V=188

    // ---- gather final 188 elements (all in x half) ----
    __syncwarp();
    #pragma unroll
    for (int c = 0; c < 6; c++) stg[lane * 6 + c] = p[c].x;   // fills [0,192)
    __syncwarp();

    // ---- FC 188->91 + sigmoid: lane handles outputs {lane, lane+32, lane+64} ----
    {
        const float2* hv2 = reinterpret_cast<const float2*>(stg);
        const float2* fw2 = reinterpret_cast<const float2*>(fc_w);
        float2 acc[3];
        #pragma unroll
        for (int u = 0; u < 3; u++) acc[u] = make_float2(0.0f, 0.0f);
        int o0 = lane, o1 = lane + 32, o2 = lane + 64;
        int c2 = (o2 < FC_OUT) ? o2 : (FC_OUT - 1);
        const float2* r0w = fw2 + (size_t)o0 * (FC_IN / 2);
        const float2* r1w = fw2 + (size_t)o1 * (FC_IN / 2);
        const float2* r2w = fw2 + (size_t)c2 * (FC_IN / 2);
        #pragma unroll 2
        for (int j = 0; j < FC_IN / 2; j++) {
            float2 hv = hv2[j];
            acc[0] = ffma2(__ldg(&r0w[j]), hv, acc[0]);
            acc[1] = ffma2(__ldg(&r1w[j]), hv, acc[1]);
            acc[2] = ffma2(__ldg(&r2w[j]), hv, acc[2]);
        }
        float* orow = out + (size_t)row * FC_OUT;
        float s0 = acc[0].x + acc[0].y + __ldg(&fc_b[o0]);
        float s1 = acc[1].x + acc[1].y + __ldg(&fc_b[o1]);
        orow[o0] = 1.0f / (1.0f + __expf(-s0));
        orow[o1] = 1.0f / (1.0f + __expf(-s1));
        if (o2 < FC_OUT) {
            float s2 = acc[2].x + acc[2].y + __ldg(&fc_b[o2]);
            orow[o2] = 1.0f / (1.0f + __expf(-s2));
        }
    }
}

extern "C" void kernel_launch(void* const* d_in, const int* in_sizes, int n_in,
                              void* d_out, int out_size)
{
    const float* x      = (const float*)d_in[0];   // [1024, 1388]
    const float* conv_w = (const float*)d_in[1];   // [200, 7]
    const float* conv_b = (const float*)d_in[2];   // [200]
    const float* fc_w   = (const float*)d_in[3];   // [91, 188]
    const float* fc_b   = (const float*)d_in[4];   // [91]
    float* out          = (float*)d_out;           // [1024, 91]

    // Pack (w,w)/(b,b) pairs into constant memory with pitched D2D copies
    // (graph-capturable memcpy nodes; no allocations).
    void* ws_ptr = nullptr; void* bs_ptr = nullptr;
    cudaGetSymbolAddress(&ws_ptr, cws);
    cudaGetSymbolAddress(&bs_ptr, cbs);
    cudaMemcpy2DAsync(ws_ptr, 8, conv_w, 4, 4, NLAYERS * KSIZE,
                      cudaMemcpyDeviceToDevice);
    cudaMemcpy2DAsync((char*)ws_ptr + 4, 8, conv_w, 4, 4, NLAYERS * KSIZE,
                      cudaMemcpyDeviceToDevice);
    cudaMemcpy2DAsync(bs_ptr, 8, conv_b, 4, 4, NLAYERS,
                      cudaMemcpyDeviceToDevice);
    cudaMemcpy2DAsync((char*)bs_ptr + 4, 8, conv_b, 4, 4, NLAYERS,
                      cudaMemcpyDeviceToDevice);

    const int B = in_sizes[0] / L_IN;              // 1024 rows
    conv200_kernel<<<GRID, NT>>>(x, fc_w, fc_b, out, B);
}